// round 8
// baseline (speedup 1.0000x reference)
#include <cuda_runtime.h>
#include <cstdint>

#define QN 8192
#define SN 30
#define DN 512

constexpr int THREADS = 896;            // 28 warps
constexpr int GRID    = 148;
constexpr int ROWS    = 2;              // q rows per warp (full 512 d each)
constexpr int NTILE   = QN / ROWS;      // 4096
constexpr int QCHUNK  = 64;             // floats per row per staged chunk
constexpr int NCHUNK  = DN / QCHUNK;    // 8
constexpr int NBUF    = 3;              // cp.async pipeline depth
constexpr int STRIDE  = 516;            // support smem stride: conflict-free

typedef unsigned long long ull;

__device__ __forceinline__ ull psub(ull a, ull b) {
    ull r; asm("sub.rn.f32x2 %0, %1, %2;" : "=l"(r) : "l"(a), "l"(b)); return r;
}
__device__ __forceinline__ ull pfma(ull a, ull b, ull c) {
    ull r; asm("fma.rn.f32x2 %0, %1, %2, %3;" : "=l"(r) : "l"(a), "l"(b), "l"(c)); return r;
}
__device__ __forceinline__ float plo(ull a) { return __uint_as_float((unsigned)(a & 0xffffffffu)); }
__device__ __forceinline__ float phi(ull a) { return __uint_as_float((unsigned)(a >> 32)); }
__device__ __forceinline__ void cpasync16(uint32_t dst, const float* src) {
    asm volatile("cp.async.ca.shared.global [%0], [%1], 16;" :: "r"(dst), "l"(src));
}

#define ABS2 0x7fffffff7fffffffULL

__global__ __launch_bounds__(THREADS, 1)
void resus_kernel(const float* __restrict__ qenc,
                  const float* __restrict__ senc,
                  const float* __restrict__ sy,
                  const float* __restrict__ sp,
                  const float* __restrict__ qp,
                  const float* __restrict__ w,
                  const float* __restrict__ ascale,
                  const float* __restrict__ abias,
                  const int*   __restrict__ nsamp,
                  float* __restrict__ out)
{
    extern __shared__ float sh[];
    float* sT  = sh;                 // [32][STRIDE] supports (30 real + 2 zero)
    float* wSh = sT + 32 * STRIDE;   // [512]
    float* qB  = wSh + DN;           // [28 warps][NBUF][ROWS][QCHUNK]

    const int tid  = threadIdx.x;
    const int lane = tid & 31;
    const int warp = tid >> 5;

    for (int idx = tid; idx < 32 * DN; idx += THREADS) {
        int s = idx >> 9, d = idx & (DN - 1);
        sT[s * STRIDE + d] = (s < SN) ? senc[idx] : 0.0f;
    }
    for (int d = tid; d < DN; d += THREADS) wSh[d] = w[d];

    float dyv = 0.0f;
    if (lane < SN) dyv = sy[lane] - 1.0f / (1.0f + __expf(-sp[lane]));
    const int ia = nsamp[0] - 1;
    const float scl = fabsf(ascale[ia]);
    const float bia = abias[ia];
    __syncthreads();

    const int tile = blockIdx.x * 28 + warp;
    if (tile >= NTILE) return;

    const float* qbase = qenc + (size_t)tile * ROWS * DN;
    float* qw = qB + warp * (NBUF * ROWS * QCHUNK);
    const uint32_t qwS = (uint32_t)__cvta_generic_to_shared(qw);
    const float* sRow = sT + lane * STRIDE;

    ull aS[ROWS], aL[ROWS];
#pragma unroll
    for (int r = 0; r < ROWS; r++) { aS[r] = 0; aL[r] = 0; }

    // Stage one 2-row x 64-float chunk: exactly 16B per lane.
    auto stageChunk = [&](int c, int b) {
        int r   = lane >> 4;           // 0..1
        int col = (lane & 15) * 4;     // 0..60
        const float* src = qbase + (size_t)r * DN + c * QCHUNK + col;
        uint32_t dst = qwS + (uint32_t)((b * ROWS * QCHUNK + r * QCHUNK + col) * 4);
        cpasync16(dst, src);
        asm volatile("cp.async.commit_group;" ::: "memory");
    };

    // Software-pipelined chunk compute: sub-iter t+1's loads issued before
    // sub-iter t's math, so the LDS->use distance covers the 29-cyc latency.
    auto computeChunk = [&](int c, int b) {
        const float* qbuf = qw + b * ROWS * QCHUNK;
        const float* sC   = sRow + c * QCHUNK;
        const float* wC   = wSh + c * QCHUNK;

        ulonglong2 sv = *reinterpret_cast<const ulonglong2*>(sC);
        ulonglong2 wv = *reinterpret_cast<const ulonglong2*>(wC);
        ulonglong2 q0 = *reinterpret_cast<const ulonglong2*>(qbuf);
        ulonglong2 q1 = *reinterpret_cast<const ulonglong2*>(qbuf + QCHUNK);

#pragma unroll
        for (int t = 0; t < QCHUNK / 4; t++) {
            ulonglong2 svn, wvn, q0n, q1n;
            if (t + 1 < QCHUNK / 4) {
                svn = *reinterpret_cast<const ulonglong2*>(sC + (t + 1) * 4);
                wvn = *reinterpret_cast<const ulonglong2*>(wC + (t + 1) * 4);
                q0n = *reinterpret_cast<const ulonglong2*>(qbuf + (t + 1) * 4);
                q1n = *reinterpret_cast<const ulonglong2*>(qbuf + QCHUNK + (t + 1) * 4);
            }
            ull d0 = psub(q0.x, sv.x);
            ull d1 = psub(q0.y, sv.y);
            aL[0] = pfma(d0, d0, aL[0]);
            aL[0] = pfma(d1, d1, aL[0]);
            aS[0] = pfma(d0 & ABS2, wv.x, aS[0]);
            aS[0] = pfma(d1 & ABS2, wv.y, aS[0]);

            ull e0 = psub(q1.x, sv.x);
            ull e1 = psub(q1.y, sv.y);
            aL[1] = pfma(e0, e0, aL[1]);
            aL[1] = pfma(e1, e1, aL[1]);
            aS[1] = pfma(e0 & ABS2, wv.x, aS[1]);
            aS[1] = pfma(e1 & ABS2, wv.y, aS[1]);

            sv = svn; wv = wvn; q0 = q0n; q1 = q1n;
        }
    };

    // 3-deep cp.async pipeline over 8 chunks.
    stageChunk(0, 0);
    stageChunk(1, 1);
    stageChunk(2, 2);

#define STEP(K, WAITN)                                                   \
    do {                                                                 \
        asm volatile("cp.async.wait_group %0;" :: "n"(WAITN) : "memory");\
        __syncwarp();                                                    \
        computeChunk(K, (K) % NBUF);                                     \
        if ((K) + NBUF < NCHUNK) stageChunk((K) + NBUF, (K) % NBUF);     \
    } while (0)

    STEP(0, 2); STEP(1, 2); STEP(2, 2); STEP(3, 2);
    STEP(4, 2); STEP(5, 2); STEP(6, 1); STEP(7, 0);
#undef STEP

    // Epilogue: lane = support. Finalize, mask, warp-reduce, write 2 rows.
    float sc[ROWS], l2[ROWS];
#pragma unroll
    for (int r = 0; r < ROWS; r++) {
        sc[r] = plo(aS[r]) + phi(aS[r]);
        l2[r] = __fsqrt_rn(plo(aL[r]) + phi(aL[r]));
        if (lane >= SN) { sc[r] = -3.4e38f; l2[r] = 0.0f; }
    }

    float m[ROWS];
#pragma unroll
    for (int r = 0; r < ROWS; r++) m[r] = sc[r];
#pragma unroll
    for (int d = 16; d; d >>= 1)
#pragma unroll
        for (int r = 0; r < ROWS; r++)
            m[r] = fmaxf(m[r], __shfl_xor_sync(0xffffffffu, m[r], d));

    float se[ROWS], sd[ROWS], sl[ROWS];
#pragma unroll
    for (int r = 0; r < ROWS; r++) {
        float e = __expf(sc[r] - m[r]);
        se[r] = e; sd[r] = e * dyv; sl[r] = l2[r];
    }
#pragma unroll
    for (int d = 16; d; d >>= 1)
#pragma unroll
        for (int r = 0; r < ROWS; r++) {
            se[r] += __shfl_xor_sync(0xffffffffu, se[r], d);
            sd[r] += __shfl_xor_sync(0xffffffffu, sd[r], d);
            sl[r] += __shfl_xor_sync(0xffffffffu, sl[r], d);
        }

    if (lane == 0) {
        const int r0 = tile * ROWS;
#pragma unroll
        for (int r = 0; r < ROWS; r++) {
            out[r0 + r]      = (sd[r] / se[r]) * scl + bia + qp[r0 + r];
            out[QN + r0 + r] = sl[r] * (1.0f / (float)SN);
        }
    }
}

extern "C" void kernel_launch(void* const* d_in, const int* in_sizes, int n_in,
                              void* d_out, int out_size) {
    const float* qenc   = (const float*)d_in[0];
    const float* senc   = (const float*)d_in[1];
    const float* sy     = (const float*)d_in[2];
    const float* sp     = (const float*)d_in[3];
    const float* qp     = (const float*)d_in[4];
    const float* w      = (const float*)d_in[5];
    // d_in[6] = fc1_b (softmax-invariant, unused)
    const float* ascale = (const float*)d_in[7];
    const float* abias  = (const float*)d_in[8];
    const int*   nsamp  = (const int*)d_in[9];

    float* out = (float*)d_out;

    // smem floats: supports 32*516 + w 512 + qBuf 28*NBUF*2*64
    const int smemFloats = 32 * STRIDE + DN + 28 * NBUF * ROWS * QCHUNK;
    const int smemBytes = smemFloats * (int)sizeof(float); // ~111 KB
    cudaFuncSetAttribute(resus_kernel,
                         cudaFuncAttributeMaxDynamicSharedMemorySize, smemBytes);

    resus_kernel<<<GRID, THREADS, smemBytes>>>(qenc, senc, sy, sp, qp, w,
                                               ascale, abias, nsamp, out);
}

// round 9
// speedup vs baseline: 1.0408x; 1.0408x over previous
#include <cuda_runtime.h>
#include <cstdint>

#define QN 8192
#define SN 30
#define DN 512

constexpr int THREADS   = 896;             // 28 warps = 14 pairs
constexpr int GRID      = 148;
constexpr int ROWS      = 4;               // q rows per tile
constexpr int NTILE     = QN / ROWS;       // 2048
constexpr int DHALF     = 256;             // d per warp (pair splits d)
constexpr int QCHUNK    = 64;              // floats per row per staged chunk
constexpr int NCHUNK    = DHALF / QCHUNK;  // 4 (all staged upfront)
constexpr int STRIDE    = 516;             // support smem stride: conflict-free
constexpr int PAIRS_BLK = 14;

typedef unsigned long long ull;

__device__ __forceinline__ ull psub(ull a, ull b) {
    ull r; asm("sub.rn.f32x2 %0, %1, %2;" : "=l"(r) : "l"(a), "l"(b)); return r;
}
__device__ __forceinline__ ull pfma(ull a, ull b, ull c) {
    ull r; asm("fma.rn.f32x2 %0, %1, %2, %3;" : "=l"(r) : "l"(a), "l"(b), "l"(c)); return r;
}
__device__ __forceinline__ float plo(ull a) { return __uint_as_float((unsigned)(a & 0xffffffffu)); }
__device__ __forceinline__ float phi(ull a) { return __uint_as_float((unsigned)(a >> 32)); }
__device__ __forceinline__ void cpasync16(uint32_t dst, const float* src) {
    asm volatile("cp.async.ca.shared.global [%0], [%1], 16;" :: "r"(dst), "l"(src));
}

#define ABS2 0x7fffffff7fffffffULL

__global__ __launch_bounds__(THREADS, 1)
void resus_kernel(const float* __restrict__ qenc,
                  const float* __restrict__ senc,
                  const float* __restrict__ sy,
                  const float* __restrict__ sp,
                  const float* __restrict__ qp,
                  const float* __restrict__ w,
                  const float* __restrict__ ascale,
                  const float* __restrict__ abias,
                  const int*   __restrict__ nsamp,
                  float* __restrict__ out)
{
    extern __shared__ float sh[];
    float* sT  = sh;                             // [32][STRIDE] supports
    float* wSh = sT + 32 * STRIDE;               // [512]
    float* qB  = wSh + DN;                       // [28 warps][NCHUNK][ROWS][QCHUNK]
    float* cmb = qB + 28 * NCHUNK * ROWS * QCHUNK; // [14 pairs][2][ROWS][32] float2

    const int tid  = threadIdx.x;
    const int lane = tid & 31;
    const int warp = tid >> 5;

    const int pairIB = warp % 14;
    const int half   = warp / 14;
    const int tile   = blockIdx.x * PAIRS_BLK + pairIB;
    const bool active = (tile < NTILE);

    const float* qbase = qenc + (size_t)tile * ROWS * DN + half * DHALF;
    float* qw = qB + warp * (NCHUNK * ROWS * QCHUNK);
    const uint32_t qwS = (uint32_t)__cvta_generic_to_shared(qw);

    // === Stage the ENTIRE q tile-half up front (4 commit groups). ===
    // The DRAM latency of these overlaps the support-staging + barrier below,
    // so the per-chunk wait_group calls in the compute phase are ~free.
    if (active) {
#pragma unroll
        for (int c = 0; c < NCHUNK; c++) {
#pragma unroll
            for (int i = 0; i < 2; i++) {
                int seg = lane + 32 * i;          // 0..63
                int r   = seg >> 4;               // 0..3
                int col = (seg & 15) * 4;         // 16B per lane
                const float* src = qbase + (size_t)r * DN + c * QCHUNK + col;
                uint32_t dst = qwS + (uint32_t)((c * ROWS * QCHUNK + r * QCHUNK + col) * 4);
                cpasync16(dst, src);
            }
            asm volatile("cp.async.commit_group;" ::: "memory");
        }
    }

    // === Support + w staging (long enough to hide the cp.async latency). ===
    for (int idx = tid; idx < 32 * DN; idx += THREADS) {
        int s = idx >> 9, d = idx & (DN - 1);
        sT[s * STRIDE + d] = (s < SN) ? senc[idx] : 0.0f;
    }
    for (int d = tid; d < DN; d += THREADS) wSh[d] = w[d];

    float dyv = 0.0f;
    if (lane < SN) dyv = sy[lane] - 1.0f / (1.0f + __expf(-sp[lane]));
    const int ia = nsamp[0] - 1;
    const float scl = fabsf(ascale[ia]);
    const float bia = abias[ia];
    __syncthreads();

    if (!active) return;

    const float* sRow = sT + lane * STRIDE + half * DHALF;
    const float* wRow = wSh + half * DHALF;

    ull aS[ROWS], aL[ROWS];
#pragma unroll
    for (int r = 0; r < ROWS; r++) { aS[r] = 0; aL[r] = 0; }

    auto computeChunk = [&](int c) {
        const float* qbuf = qw + c * ROWS * QCHUNK;
        const float* sC   = sRow + c * QCHUNK;
        const float* wC   = wRow + c * QCHUNK;
#pragma unroll 8
        for (int t = 0; t < QCHUNK / 4; t++) {
            ulonglong2 sv = *reinterpret_cast<const ulonglong2*>(sC + t * 4);
            ulonglong2 wv = *reinterpret_cast<const ulonglong2*>(wC + t * 4);
#pragma unroll
            for (int r = 0; r < ROWS; r++) {
                ulonglong2 qv = *reinterpret_cast<const ulonglong2*>(qbuf + r * QCHUNK + t * 4);
                ull d0 = psub(qv.x, sv.x);
                ull d1 = psub(qv.y, sv.y);
                aL[r] = pfma(d0, d0, aL[r]);
                aL[r] = pfma(d1, d1, aL[r]);
                aS[r] = pfma(d0 & ABS2, wv.x, aS[r]);
                aS[r] = pfma(d1 & ABS2, wv.y, aS[r]);
            }
        }
    };

    // Progressive waits: group k must be complete before chunk k.
    asm volatile("cp.async.wait_group 3;" ::: "memory"); __syncwarp();
    computeChunk(0);
    asm volatile("cp.async.wait_group 2;" ::: "memory"); __syncwarp();
    computeChunk(1);
    asm volatile("cp.async.wait_group 1;" ::: "memory"); __syncwarp();
    computeChunk(2);
    asm volatile("cp.async.wait_group 0;" ::: "memory"); __syncwarp();
    computeChunk(3);

    // ---- Pair combine: partials per (row, lane=support), sqrt AFTER combining ----
    float2* cp2 = reinterpret_cast<float2*>(cmb) + pairIB * (2 * ROWS * 32);
#pragma unroll
    for (int r = 0; r < ROWS; r++) {
        float scP  = plo(aS[r]) + phi(aS[r]);
        float ssqP = plo(aL[r]) + phi(aL[r]);
        cp2[(half * ROWS + r) * 32 + lane] = make_float2(scP, ssqP);
    }
    asm volatile("bar.sync %0, 64;" :: "r"(1 + pairIB) : "memory");

    // Each warp of the pair finishes 2 rows.
#pragma unroll
    for (int k = 0; k < 2; k++) {
        const int r = half * 2 + k;
        float2 pa = cp2[(0 * ROWS + r) * 32 + lane];
        float2 pb = cp2[(1 * ROWS + r) * 32 + lane];
        float sc  = pa.x + pb.x;
        float l2v = __fsqrt_rn(pa.y + pb.y);
        if (lane >= SN) { sc = -3.4e38f; l2v = 0.0f; }

        float m = sc;
#pragma unroll
        for (int d = 16; d; d >>= 1) m = fmaxf(m, __shfl_xor_sync(0xffffffffu, m, d));
        float e  = __expf(sc - m);
        float se = e, sd = e * dyv, sl = l2v;
#pragma unroll
        for (int d = 16; d; d >>= 1) {
            se += __shfl_xor_sync(0xffffffffu, se, d);
            sd += __shfl_xor_sync(0xffffffffu, sd, d);
            sl += __shfl_xor_sync(0xffffffffu, sl, d);
        }
        if (lane == 0) {
            const int row = tile * ROWS + r;
            out[row]      = (sd / se) * scl + bia + qp[row];
            out[QN + row] = sl * (1.0f / (float)SN);
        }
    }
}

extern "C" void kernel_launch(void* const* d_in, const int* in_sizes, int n_in,
                              void* d_out, int out_size) {
    const float* qenc   = (const float*)d_in[0];
    const float* senc   = (const float*)d_in[1];
    const float* sy     = (const float*)d_in[2];
    const float* sp     = (const float*)d_in[3];
    const float* qp     = (const float*)d_in[4];
    const float* w      = (const float*)d_in[5];
    // d_in[6] = fc1_b (softmax-invariant, unused)
    const float* ascale = (const float*)d_in[7];
    const float* abias  = (const float*)d_in[8];
    const int*   nsamp  = (const int*)d_in[9];

    float* out = (float*)d_out;

    // smem floats: supports 32*516 + w 512 + qBuf 28*4*4*64 + combine 14*2*4*32*2
    const int smemFloats = 32 * STRIDE + DN
                         + 28 * NCHUNK * ROWS * QCHUNK
                         + PAIRS_BLK * 2 * ROWS * 32 * 2;
    const int smemBytes = smemFloats * (int)sizeof(float); // ~207 KB
    cudaFuncSetAttribute(resus_kernel,
                         cudaFuncAttributeMaxDynamicSharedMemorySize, smemBytes);

    resus_kernel<<<GRID, THREADS, smemBytes>>>(qenc, senc, sy, sp, qp, w,
                                               ascale, abias, nsamp, out);
}

// round 11
// speedup vs baseline: 1.0837x; 1.0413x over previous
#include <cuda_runtime.h>
#include <cstdint>

#define QN 8192
#define SN 30
#define DN 512

constexpr int THREADS = 896;            // 28 warps = 7 groups of 4
constexpr int GRID    = 148;
constexpr int ROWS    = 8;              // q rows per tile
constexpr int NTILE   = QN / ROWS;      // 1024
constexpr int DQ      = 128;            // d per warp (4-way split)
constexpr int STRIDE  = 516;            // support smem stride (floats): conflict-free
constexpr int GROUPS  = 7;

typedef unsigned long long ull;

__device__ __forceinline__ ull psub(ull a, ull b) {
    ull r; asm("sub.rn.f32x2 %0, %1, %2;" : "=l"(r) : "l"(a), "l"(b)); return r;
}
__device__ __forceinline__ ull pfma(ull a, ull b, ull c) {
    ull r; asm("fma.rn.f32x2 %0, %1, %2, %3;" : "=l"(r) : "l"(a), "l"(b), "l"(c)); return r;
}
__device__ __forceinline__ float plo(ull a) { return __uint_as_float((unsigned)(a & 0xffffffffu)); }
__device__ __forceinline__ float phi(ull a) { return __uint_as_float((unsigned)(a >> 32)); }
__device__ __forceinline__ void cpasync16(uint32_t dst, const float* src) {
    asm volatile("cp.async.ca.shared.global [%0], [%1], 16;" :: "r"(dst), "l"(src));
}
// Shared-state-space 128-bit load; 32-bit address lets ptxas fold constant
// offsets into LDS immediates (zero per-load ALU).
__device__ __forceinline__ void lds128(uint32_t addr, ull& lo, ull& hi) {
    asm volatile("ld.shared.v2.b64 {%0, %1}, [%2];" : "=l"(lo), "=l"(hi) : "r"(addr));
}

#define ABS2 0x7fffffff7fffffffULL

__global__ __launch_bounds__(THREADS, 1)
void resus_kernel(const float* __restrict__ qenc,
                  const float* __restrict__ senc,
                  const float* __restrict__ sy,
                  const float* __restrict__ sp,
                  const float* __restrict__ qp,
                  const float* __restrict__ w,
                  const float* __restrict__ ascale,
                  const float* __restrict__ abias,
                  const int*   __restrict__ nsamp,
                  float* __restrict__ out)
{
    extern __shared__ float sh[];
    float* sT  = sh;                 // [32][STRIDE] supports (30 real + 2 zero)
    float* wSh = sT + 32 * STRIDE;   // [512]
    float* qB  = wSh + DN;           // [28 warps][ROWS][DQ] staged q (4 KB/warp)
                                     // (reused as combine scratch AFTER a barrier)

    const int tid  = threadIdx.x;
    const int lane = tid & 31;
    const int warp = tid >> 5;

    const int group   = warp >> 2;       // 0..6
    const int quarter = warp & 3;        // d-quarter this warp owns
    const int tile    = blockIdx.x * GROUPS + group;
    const bool active = (tile < NTILE);

    float* qw = qB + warp * (ROWS * DQ);
    const uint32_t qwS = (uint32_t)__cvta_generic_to_shared(qw);

    // === Upfront cp.async: stage this warp's 8-row x 128-d quarter (4 KB). ===
    if (active) {
        const float* qbase = qenc + (size_t)tile * ROWS * DN + quarter * DQ;
#pragma unroll
        for (int r = 0; r < ROWS; r++) {
            cpasync16(qwS + (uint32_t)((r * DQ + lane * 4) * 4),
                      qbase + (size_t)r * DN + lane * 4);
        }
        asm volatile("cp.async.commit_group;" ::: "memory");
    }

    // === Support + w staging (hides the cp.async DRAM latency). ===
    for (int idx = tid; idx < 32 * DN; idx += THREADS) {
        int s = idx >> 9, d = idx & (DN - 1);
        sT[s * STRIDE + d] = (s < SN) ? senc[idx] : 0.0f;
    }
    for (int d = tid; d < DN; d += THREADS) wSh[d] = w[d];

    float dyv = 0.0f;
    if (lane < SN) dyv = sy[lane] - 1.0f / (1.0f + __expf(-sp[lane]));
    const int ia = nsamp[0] - 1;
    const float scl = fabsf(ascale[ia]);
    const float bia = abias[ia];
    __syncthreads();

    if (!active) return;

    const uint32_t sBase = (uint32_t)__cvta_generic_to_shared(
                               sT + lane * STRIDE + quarter * DQ);
    const uint32_t wBase = (uint32_t)__cvta_generic_to_shared(wSh + quarter * DQ);

    asm volatile("cp.async.wait_group 0;" ::: "memory");
    __syncwarp();

    ull aS[ROWS], aL[ROWS];
#pragma unroll
    for (int r = 0; r < ROWS; r++) { aS[r] = 0; aL[r] = 0; }

    // === Hot loop: 32 sub-iters x (10 LDS.128 + 8x6 packed math), unrolled. ===
#pragma unroll
    for (int t = 0; t < DQ / 4; t++) {
        ull svx, svy, wvx, wvy;
        lds128(sBase + t * 16, svx, svy);   // lane-strided: conflict-free phases
        lds128(wBase + t * 16, wvx, wvy);   // broadcast
#pragma unroll
        for (int r = 0; r < ROWS; r++) {
            ull qx, qy;
            lds128(qwS + (uint32_t)(r * DQ * 4 + t * 16), qx, qy);  // broadcast
            ull d0 = psub(qx, svx);
            ull d1 = psub(qy, svy);
            aL[r] = pfma(d0, d0, aL[r]);
            aL[r] = pfma(d1, d1, aL[r]);
            aS[r] = pfma(d0 & ABS2, wvx, aS[r]);
            aS[r] = pfma(d1 & ABS2, wvy, aS[r]);
        }
    }

    // === Quarter combine. The group's qB staging region is reused as scratch,
    // but ONLY after all 4 warps of the group stop reading their staged q:
    // barrier -> write -> barrier -> read. (R10's race: wrote before barrier.)
    asm volatile("bar.sync %0, 128;" :: "r"(1 + group) : "memory");

    float2* cmb = reinterpret_cast<float2*>(qB + group * 4 * ROWS * DQ);
#pragma unroll
    for (int r = 0; r < ROWS; r++) {
        cmb[(quarter * ROWS + r) * 32 + lane] =
            make_float2(plo(aS[r]) + phi(aS[r]), plo(aL[r]) + phi(aL[r]));
    }
    asm volatile("bar.sync %0, 128;" :: "r"(1 + group) : "memory");

    // Each warp of the group finalizes 2 rows (lane = support).
#pragma unroll
    for (int k = 0; k < 2; k++) {
        const int r = quarter * 2 + k;
        float sc = 0.0f, ssq = 0.0f;
#pragma unroll
        for (int qd = 0; qd < 4; qd++) {
            float2 p = cmb[(qd * ROWS + r) * 32 + lane];
            sc += p.x; ssq += p.y;
        }
        float l2v = __fsqrt_rn(ssq);
        if (lane >= SN) { sc = -3.4e38f; l2v = 0.0f; }

        float m = sc;
#pragma unroll
        for (int d = 16; d; d >>= 1) m = fmaxf(m, __shfl_xor_sync(0xffffffffu, m, d));
        float e  = __expf(sc - m);
        float se = e, sd = e * dyv, sl = l2v;
#pragma unroll
        for (int d = 16; d; d >>= 1) {
            se += __shfl_xor_sync(0xffffffffu, se, d);
            sd += __shfl_xor_sync(0xffffffffu, sd, d);
            sl += __shfl_xor_sync(0xffffffffu, sl, d);
        }
        if (lane == 0) {
            const int row = tile * ROWS + r;
            out[row]      = (sd / se) * scl + bia + qp[row];
            out[QN + row] = sl * (1.0f / (float)SN);
        }
    }
}

extern "C" void kernel_launch(void* const* d_in, const int* in_sizes, int n_in,
                              void* d_out, int out_size) {
    const float* qenc   = (const float*)d_in[0];
    const float* senc   = (const float*)d_in[1];
    const float* sy     = (const float*)d_in[2];
    const float* sp     = (const float*)d_in[3];
    const float* qp     = (const float*)d_in[4];
    const float* w      = (const float*)d_in[5];
    // d_in[6] = fc1_b (softmax-invariant, unused)
    const float* ascale = (const float*)d_in[7];
    const float* abias  = (const float*)d_in[8];
    const int*   nsamp  = (const int*)d_in[9];

    float* out = (float*)d_out;

    // smem floats: supports 32*516 + w 512 + qStage 28*8*128
    const int smemFloats = 32 * STRIDE + DN + 28 * ROWS * DQ;
    const int smemBytes = smemFloats * (int)sizeof(float); // ~183 KB
    cudaFuncSetAttribute(resus_kernel,
                         cudaFuncAttributeMaxDynamicSharedMemorySize, smemBytes);

    resus_kernel<<<GRID, THREADS, smemBytes>>>(qenc, senc, sy, sp, qp, w,
                                               ascale, abias, nsamp, out);
}

// round 12
// speedup vs baseline: 1.0863x; 1.0024x over previous
#include <cuda_runtime.h>
#include <cstdint>

#define QN 8192
#define SN 30
#define DN 512

constexpr int THREADS = 896;            // 28 warps = 7 groups of 4
constexpr int GRID    = 148;
constexpr int ROWS    = 8;              // q rows per tile
constexpr int NTILE   = QN / ROWS;      // 1024
constexpr int DQ      = 128;            // d per warp (4-way split)
constexpr int STRIDE  = 516;            // support smem stride (floats): conflict-free
constexpr int GROUPS  = 7;

typedef unsigned long long ull;

__device__ __forceinline__ ull psub(ull a, ull b) {
    ull r; asm("sub.rn.f32x2 %0, %1, %2;" : "=l"(r) : "l"(a), "l"(b)); return r;
}
// Tied-accumulator packed FMA: in/out share one register pair, so ptxas emits
// a single FFMA2 with no 64-bit MOV shuffling around the accumulator.
__device__ __forceinline__ void pfma_acc(ull& acc, ull a, ull b) {
    asm("fma.rn.f32x2 %0, %1, %2, %0;" : "+l"(acc) : "l"(a), "l"(b));
}
__device__ __forceinline__ float plo(ull a) { return __uint_as_float((unsigned)(a & 0xffffffffu)); }
__device__ __forceinline__ float phi(ull a) { return __uint_as_float((unsigned)(a >> 32)); }
__device__ __forceinline__ void cpasync16(uint32_t dst, const float* src) {
    asm volatile("cp.async.ca.shared.global [%0], [%1], 16;" :: "r"(dst), "l"(src));
}
__device__ __forceinline__ void lds128(uint32_t addr, ull& lo, ull& hi) {
    asm volatile("ld.shared.v2.b64 {%0, %1}, [%2];" : "=l"(lo), "=l"(hi) : "r"(addr));
}

#define ABS2 0x7fffffff7fffffffULL

__global__ __launch_bounds__(THREADS, 1)
void resus_kernel(const float* __restrict__ qenc,
                  const float* __restrict__ senc,
                  const float* __restrict__ sy,
                  const float* __restrict__ sp,
                  const float* __restrict__ qp,
                  const float* __restrict__ w,
                  const float* __restrict__ ascale,
                  const float* __restrict__ abias,
                  const int*   __restrict__ nsamp,
                  float* __restrict__ out)
{
    extern __shared__ float sh[];
    float* sT  = sh;                 // [32][STRIDE] supports (30 real + 2 zero)
    float* wSh = sT + 32 * STRIDE;   // [512]
    float* qB  = wSh + DN;           // [28 warps][ROWS][DQ] staged q (4 KB/warp)

    const int tid  = threadIdx.x;
    const int lane = tid & 31;
    const int warp = tid >> 5;

    const int group   = warp >> 2;       // 0..6
    const int quarter = warp & 3;        // d-quarter this warp owns
    const int tile    = blockIdx.x * GROUPS + group;
    const bool active = (tile < NTILE);

    float* qw = qB + warp * (ROWS * DQ);
    const uint32_t qwS = (uint32_t)__cvta_generic_to_shared(qw);

    // === Upfront cp.async: stage this warp's 8-row x 128-d quarter (4 KB). ===
    if (active) {
        const float* qbase = qenc + (size_t)tile * ROWS * DN + quarter * DQ;
#pragma unroll
        for (int r = 0; r < ROWS; r++) {
            cpasync16(qwS + (uint32_t)((r * DQ + lane * 4) * 4),
                      qbase + (size_t)r * DN + lane * 4);
        }
        asm volatile("cp.async.commit_group;" ::: "memory");
    }

    // === Support + w staging (hides the cp.async DRAM latency). ===
    for (int idx = tid; idx < 32 * DN; idx += THREADS) {
        int s = idx >> 9, d = idx & (DN - 1);
        sT[s * STRIDE + d] = (s < SN) ? senc[idx] : 0.0f;
    }
    for (int d = tid; d < DN; d += THREADS) wSh[d] = w[d];

    float dyv = 0.0f;
    if (lane < SN) dyv = sy[lane] - 1.0f / (1.0f + __expf(-sp[lane]));
    const int ia = nsamp[0] - 1;
    const float scl = fabsf(ascale[ia]);
    const float bia = abias[ia];
    __syncthreads();

    if (!active) return;

    const uint32_t sBase = (uint32_t)__cvta_generic_to_shared(
                               sT + lane * STRIDE + quarter * DQ);
    const uint32_t wBase = (uint32_t)__cvta_generic_to_shared(wSh + quarter * DQ);

    asm volatile("cp.async.wait_group 0;" ::: "memory");
    __syncwarp();

    ull aS[ROWS], aL[ROWS];
#pragma unroll
    for (int r = 0; r < ROWS; r++) { aS[r] = 0; aL[r] = 0; }

    // === Hot loop: 32 sub-iters x (10 LDS.128 + packed math), fully unrolled.
    // All accumulation through tied-operand FFMA2 (no hidden MOVs). ===
#pragma unroll
    for (int t = 0; t < DQ / 4; t++) {
        ull svx, svy, wvx, wvy;
        lds128(sBase + t * 16, svx, svy);   // lane-strided: conflict-free phases
        lds128(wBase + t * 16, wvx, wvy);   // broadcast
#pragma unroll
        for (int r = 0; r < ROWS; r++) {
            ull qx, qy;
            lds128(qwS + (uint32_t)(r * DQ * 4 + t * 16), qx, qy);  // broadcast
            ull d0 = psub(qx, svx);
            ull d1 = psub(qy, svy);
            pfma_acc(aL[r], d0, d0);
            pfma_acc(aL[r], d1, d1);
            pfma_acc(aS[r], d0 & ABS2, wvx);
            pfma_acc(aS[r], d1 & ABS2, wvy);
        }
    }

    // === Quarter combine: barrier -> write into dead staging region -> barrier.
    asm volatile("bar.sync %0, 128;" :: "r"(1 + group) : "memory");

    float2* cmb = reinterpret_cast<float2*>(qB + group * 4 * ROWS * DQ);
#pragma unroll
    for (int r = 0; r < ROWS; r++) {
        cmb[(quarter * ROWS + r) * 32 + lane] =
            make_float2(plo(aS[r]) + phi(aS[r]), plo(aL[r]) + phi(aL[r]));
    }
    asm volatile("bar.sync %0, 128;" :: "r"(1 + group) : "memory");

    // Each warp of the group finalizes 2 rows (lane = support).
#pragma unroll
    for (int k = 0; k < 2; k++) {
        const int r = quarter * 2 + k;
        float sc = 0.0f, ssq = 0.0f;
#pragma unroll
        for (int qd = 0; qd < 4; qd++) {
            float2 p = cmb[(qd * ROWS + r) * 32 + lane];
            sc += p.x; ssq += p.y;
        }
        float l2v = __fsqrt_rn(ssq);
        if (lane >= SN) { sc = -3.4e38f; l2v = 0.0f; }

        float m = sc;
#pragma unroll
        for (int d = 16; d; d >>= 1) m = fmaxf(m, __shfl_xor_sync(0xffffffffu, m, d));
        float e  = __expf(sc - m);
        float se = e, sd = e * dyv, sl = l2v;
#pragma unroll
        for (int d = 16; d; d >>= 1) {
            se += __shfl_xor_sync(0xffffffffu, se, d);
            sd += __shfl_xor_sync(0xffffffffu, sd, d);
            sl += __shfl_xor_sync(0xffffffffu, sl, d);
        }
        if (lane == 0) {
            const int row = tile * ROWS + r;
            out[row]      = (sd / se) * scl + bia + qp[row];
            out[QN + row] = sl * (1.0f / (float)SN);
        }
    }
}

extern "C" void kernel_launch(void* const* d_in, const int* in_sizes, int n_in,
                              void* d_out, int out_size) {
    const float* qenc   = (const float*)d_in[0];
    const float* senc   = (const float*)d_in[1];
    const float* sy     = (const float*)d_in[2];
    const float* sp     = (const float*)d_in[3];
    const float* qp     = (const float*)d_in[4];
    const float* w      = (const float*)d_in[5];
    // d_in[6] = fc1_b (softmax-invariant, unused)
    const float* ascale = (const float*)d_in[7];
    const float* abias  = (const float*)d_in[8];
    const int*   nsamp  = (const int*)d_in[9];

    float* out = (float*)d_out;

    // smem floats: supports 32*516 + w 512 + qStage 28*8*128
    const int smemFloats = 32 * STRIDE + DN + 28 * ROWS * DQ;
    const int smemBytes = smemFloats * (int)sizeof(float); // ~183 KB
    cudaFuncSetAttribute(resus_kernel,
                         cudaFuncAttributeMaxDynamicSharedMemorySize, smemBytes);

    resus_kernel<<<GRID, THREADS, smemBytes>>>(qenc, senc, sy, sp, qp, w,
                                               ascale, abias, nsamp, out);
}